// round 3
// baseline (speedup 1.0000x reference)
#include <cuda_runtime.h>
#include <cstddef>

#define BSZ 256
#define TT  512
#define IND 128
#define HID 512
#define NBLK 128
#define NTHR 128

// ---------------- persistent device state (no cudaMalloc allowed) ----------
__device__ float g_zero[BSZ * HID];
__device__ float g_h1a[BSZ * HID];
__device__ float g_h1b[BSZ * HID];
__device__ float g_H2[(size_t)TT * BSZ * HID];   // h2 log [t][b][h]
__device__ unsigned g_cnt;                       // barrier arrive counter
__device__ volatile unsigned g_gen;              // barrier generation

// ---------------- packed f32x2 helpers -------------------------------------
__device__ __forceinline__ unsigned long long pack2(float x) {
    unsigned long long r;
    asm("mov.b64 %0, {%1, %1};" : "=l"(r) : "f"(x));
    return r;
}
__device__ __forceinline__ void fma2(unsigned long long& d,
                                     unsigned long long a,
                                     unsigned long long b) {
    asm("fma.rn.f32x2 %0, %1, %2, %0;" : "+l"(d) : "l"(a), "l"(b));
}
__device__ __forceinline__ float lo32(unsigned long long v) {
    return __uint_as_float((unsigned)v);
}
__device__ __forceinline__ float hi32(unsigned long long v) {
    return __uint_as_float((unsigned)(v >> 32));
}
__device__ __forceinline__ float sigm(float x) { return 1.0f / (1.0f + expf(-x)); }

// ---------------- grid-wide barrier (single wave: 128 blocks <= 148 SMs) ---
__device__ __forceinline__ void grid_sync() {
    __syncthreads();
    if (threadIdx.x == 0) {
        __threadfence();
        unsigned gen = g_gen;
        if (atomicAdd(&g_cnt, 1u) == NBLK - 1) {
            g_cnt = 0;
            __threadfence();
            g_gen = gen + 1;
        } else {
            while (g_gen == gen) __nanosleep(64);
            __threadfence();
        }
    }
    __syncthreads();
}

// ---------------- GEMM building blocks -------------------------------------
// Tile: 64 batch rows (m) x 64 gate cols (n), K-tile = 32.
// Gate col n -> weight row (n>>4)*HID + j0 + (n&15).
struct Seg { const float* A; size_t lda; const float* W; size_t ldw; };

__device__ __forceinline__ void ldg_ab(const Seg& s, int j0, int koff, int tid,
                                       float4 (&ra)[4], float4 (&rb)[4]) {
#pragma unroll
    for (int i = 0; i < 4; i++) {
        int lin = tid + i * NTHR;
        int m = lin >> 3, k4 = (lin & 7) * 4;
        ra[i] = *(const float4*)(s.A + (size_t)m * s.lda + koff + k4);
        int wr = (m >> 4) * HID + j0 + (m & 15);
        rb[i] = *(const float4*)(s.W + (size_t)wr * s.ldw + koff + k4);
    }
}

__device__ __forceinline__ void sts_ab(float* As, float* Bs, int tid,
                                       const float4 (&ra)[4], const float4 (&rb)[4]) {
#pragma unroll
    for (int i = 0; i < 4; i++) {
        int lin = tid + i * NTHR;
        int m = lin >> 3, k4 = (lin & 7) * 4;
        As[(k4 + 0) * 64 + m] = ra[i].x;
        As[(k4 + 1) * 64 + m] = ra[i].y;
        As[(k4 + 2) * 64 + m] = ra[i].z;
        As[(k4 + 3) * 64 + m] = ra[i].w;
        Bs[(k4 + 0) * 64 + m] = rb[i].x;
        Bs[(k4 + 1) * 64 + m] = rb[i].y;
        Bs[(k4 + 2) * 64 + m] = rb[i].z;
        Bs[(k4 + 3) * 64 + m] = rb[i].w;
    }
}

// acc[mp][c] packs rows (tm*8+2mp, tm*8+2mp+1) for col tn*4+c.
__device__ __forceinline__ void mm_tile(const float* As, const float* Bs,
                                        int tm, int tn,
                                        unsigned long long (&acc)[4][4]) {
#pragma unroll 8
    for (int k = 0; k < 32; k++) {
        ulonglong2 a01 = *(const ulonglong2*)(As + k * 64 + tm * 8);
        ulonglong2 a23 = *(const ulonglong2*)(As + k * 64 + tm * 8 + 4);
        float4 bv = *(const float4*)(Bs + k * 64 + tn * 4);
        unsigned long long b0 = pack2(bv.x), b1 = pack2(bv.y),
                           b2 = pack2(bv.z), b3 = pack2(bv.w);
        fma2(acc[0][0], a01.x, b0); fma2(acc[0][1], a01.x, b1);
        fma2(acc[0][2], a01.x, b2); fma2(acc[0][3], a01.x, b3);
        fma2(acc[1][0], a01.y, b0); fma2(acc[1][1], a01.y, b1);
        fma2(acc[1][2], a01.y, b2); fma2(acc[1][3], a01.y, b3);
        fma2(acc[2][0], a23.x, b0); fma2(acc[2][1], a23.x, b1);
        fma2(acc[2][2], a23.x, b2); fma2(acc[2][3], a23.x, b3);
        fma2(acc[3][0], a23.y, b0); fma2(acc[3][1], a23.y, b1);
        fma2(acc[3][2], a23.y, b2); fma2(acc[3][3], a23.y, b3);
    }
}

// Double-buffered two-segment GEMM: gates += A0@W0^T (nt0 tiles) + A1@W1^T (nt1 tiles)
__device__ __forceinline__ void gates_gemm(const Seg& s0, int nt0,
                                           const Seg& s1, int nt1,
                                           float* pool, int j0, int tid,
                                           int tm, int tn,
                                           unsigned long long (&acc)[4][4]) {
    float* As0 = pool;          float* As1 = pool + 2048;
    float* Bs0 = pool + 4096;   float* Bs1 = pool + 6144;
#pragma unroll
    for (int i = 0; i < 4; i++)
#pragma unroll
        for (int j = 0; j < 4; j++) acc[i][j] = 0ull;

    const int total = nt0 + nt1;
    float4 ra[4], rb[4];
    ldg_ab(s0, j0, 0, tid, ra, rb);
    sts_ab(As0, Bs0, tid, ra, rb);
    __syncthreads();

#pragma unroll 1
    for (int kt = 0; kt < total; kt++) {
        const int nxt = kt + 1;
        const bool has = nxt < total;
        if (has) {
            if (nxt < nt0) ldg_ab(s0, j0, nxt * 32, tid, ra, rb);
            else           ldg_ab(s1, j0, (nxt - nt0) * 32, tid, ra, rb);
        }
        const float* Ac = (kt & 1) ? As1 : As0;
        const float* Bc = (kt & 1) ? Bs1 : Bs0;
        mm_tile(Ac, Bc, tm, tn, acc);
        if (has) {
            float* An = (nxt & 1) ? As1 : As0;
            float* Bn = (nxt & 1) ? Bs1 : Bs0;
            sts_ab(An, Bn, tid, ra, rb);
        }
        __syncthreads();
    }
}

__device__ __forceinline__ void acc_to_cs(float* Cs,
                                          const unsigned long long (&acc)[4][4],
                                          int tm, int tn) {
#pragma unroll
    for (int mp = 0; mp < 4; mp++)
#pragma unroll
        for (int c = 0; c < 4; c++) {
            int n = tn * 4 + c;
            int m = tm * 8 + mp * 2;
            Cs[n * 65 + m]     = lo32(acc[mp][c]);
            Cs[n * 65 + m + 1] = hi32(acc[mp][c]);
        }
}

__device__ __forceinline__ void cell_update(const float* Cs, const float* bs,
                                            float (&cr)[8], float* hglob,
                                            int m0, int j0, int tid) {
#pragma unroll
    for (int w = 0; w < 8; w++) {
        int item = w * NTHR + tid;
        int jj = item & 15;
        int mm = item >> 4;
        float gi = Cs[(jj)      * 65 + mm] + bs[jj];
        float gf = Cs[(16 + jj) * 65 + mm] + bs[16 + jj];
        float gg = Cs[(32 + jj) * 65 + mm] + bs[32 + jj];
        float go = Cs[(48 + jj) * 65 + mm] + bs[48 + jj];
        float iv = sigm(gi), fv = sigm(gf);
        float gv = tanhf(gg), ov = sigm(go);
        float cn = fv * cr[w] + iv * gv;
        cr[w] = cn;
        hglob[(size_t)(m0 + mm) * HID + j0 + jj] = ov * tanhf(cn);
    }
}

// ============================================================================
// Persistent LSTM kernel: whole T=512 recurrence, 128 blocks, 1 launch.
// Block -> (m0 = (bid>>5)*64 batch rows, j0 = (bid&31)*16 hidden units).
// ============================================================================
__global__ __launch_bounds__(NTHR, 1) void lstm_persistent(
    const float* __restrict__ x,
    const float* __restrict__ Wih1, const float* __restrict__ Whh1,
    const float* __restrict__ bih1, const float* __restrict__ bhh1,
    const float* __restrict__ Wih2, const float* __restrict__ Whh2,
    const float* __restrict__ bih2, const float* __restrict__ bhh2)
{
    __shared__ __align__(16) float pool[8192];   // As0|As1|Bs0|Bs1 ; Cs aliases pool
    __shared__ float bs1[64], bs2[64];
    float* Cs = pool;                            // 64*65 = 4160 floats, used post-GEMM

    const int tid = threadIdx.x;
    const int bid = blockIdx.x;
    const int m0 = (bid >> 5) * 64;
    const int j0 = (bid & 31) * 16;
    const int tm = tid & 7;
    const int tn = tid >> 3;

    // zero the t=0 state buffer (16384 threads x 8 = 131072 floats)
    {
        int base = (bid * NTHR + tid) * 8;
#pragma unroll
        for (int i = 0; i < 8; i++) g_zero[base + i] = 0.0f;
    }
    // bias sums for this block's 64 gate-columns (index n = gate*16 + jj)
    if (tid < 64) {
        int wr = (tid >> 4) * HID + j0 + (tid & 15);
        bs1[tid] = bih1[wr] + bhh1[wr];
        bs2[tid] = bih2[wr] + bhh2[wr];
    }
    grid_sync();

    float c1r[8], c2r[8];
#pragma unroll
    for (int i = 0; i < 8; i++) { c1r[i] = 0.0f; c2r[i] = 0.0f; }

    unsigned long long acc[4][4];

#pragma unroll 1
    for (int t = 0; t < TT; t++) {
        const float* h1p = (t == 0) ? g_zero : ((t & 1) ? g_h1a : g_h1b);
        float*       h1c = (t & 1) ? g_h1b : g_h1a;

        // ---- layer 1: gates = x_t @ Wih1^T + h1prev @ Whh1^T --------------
        Seg s0 { x + (size_t)m0 * (TT * IND) + (size_t)t * IND, (size_t)(TT * IND), Wih1, IND };
        Seg s1 { h1p + (size_t)m0 * HID, HID, Whh1, HID };
        gates_gemm(s0, IND / 32, s1, HID / 32, pool, j0, tid, tm, tn, acc);
        acc_to_cs(Cs, acc, tm, tn);
        __syncthreads();
        cell_update(Cs, bs1, c1r, h1c, m0, j0, tid);
        grid_sync();                                   // h1(t) visible chip-wide

        // ---- layer 2: gates = h1(t) @ Wih2^T + h2(t-1) @ Whh2^T -----------
        const float* h2p = (t == 0) ? g_zero : (g_H2 + (size_t)(t - 1) * BSZ * HID);
        float*       h2c = g_H2 + (size_t)t * BSZ * HID;
        Seg s2 { h1c + (size_t)m0 * HID, HID, Wih2, HID };
        Seg s3 { h2p + (size_t)m0 * HID, HID, Whh2, HID };
        gates_gemm(s2, HID / 32, s3, HID / 32, pool, j0, tid, tm, tn, acc);
        acc_to_cs(Cs, acc, tm, tn);
        __syncthreads();
        cell_update(Cs, bs2, c2r, h2c, m0, j0, tid);
        grid_sync();                                   // h2(t) visible chip-wide
    }
}

// ============================================================================
// Output linear: out[b,t,:] = H2[t,b,:] @ Wlin^T + blin
// M = T*B = 131072 (row r = t*256+b), N = 128, K = 512. Fully parallel.
// ============================================================================
__global__ __launch_bounds__(128, 2) void linear_kernel(
    const float* __restrict__ Wl, const float* __restrict__ bl,
    float* __restrict__ out)
{
    __shared__ __align__(16) float smem[4096];
    float* As = smem;
    float* Bs = smem + 2048;

    const int tid = threadIdx.x;
    const int r0  = blockIdx.x * 64;
    const int n0  = blockIdx.y * 64;
    const int tm  = tid & 7;
    const int tn  = tid >> 3;
    const float* H2 = g_H2;

    unsigned long long acc[4][4];
#pragma unroll
    for (int i = 0; i < 4; i++)
#pragma unroll
        for (int j = 0; j < 4; j++) acc[i][j] = 0ull;

#pragma unroll 1
    for (int k0 = 0; k0 < HID; k0 += 32) {
        __syncthreads();
#pragma unroll
        for (int i = 0; i < 4; i++) {
            int lin = tid + i * 128;
            int m = lin >> 3, k4 = (lin & 7) * 4;
            float4 v = *(const float4*)(H2 + (size_t)(r0 + m) * HID + k0 + k4);
            As[(k4 + 0) * 64 + m] = v.x;
            As[(k4 + 1) * 64 + m] = v.y;
            As[(k4 + 2) * 64 + m] = v.z;
            As[(k4 + 3) * 64 + m] = v.w;
            float4 w = *(const float4*)(Wl + (size_t)(n0 + m) * HID + k0 + k4);
            Bs[(k4 + 0) * 64 + m] = w.x;
            Bs[(k4 + 1) * 64 + m] = w.y;
            Bs[(k4 + 2) * 64 + m] = w.z;
            Bs[(k4 + 3) * 64 + m] = w.w;
        }
        __syncthreads();
        mm_tile(As, Bs, tm, tn, acc);
    }

#pragma unroll
    for (int mp = 0; mp < 4; mp++) {
#pragma unroll
        for (int half = 0; half < 2; half++) {
            int r = r0 + tm * 8 + mp * 2 + half;
            int t = r >> 8;
            int b = r & 255;
            float* orow = out + (size_t)b * TT * IND + (size_t)t * IND;
#pragma unroll
            for (int c = 0; c < 4; c++) {
                int col = n0 + tn * 4 + c;
                float v = half ? hi32(acc[mp][c]) : lo32(acc[mp][c]);
                orow[col] = v + bl[col];
            }
        }
    }
}

extern "C" void kernel_launch(void* const* d_in, const int* in_sizes, int n_in,
                              void* d_out, int out_size)
{
    const float* x    = (const float*)d_in[0];
    // d_in[1] = future (0 for this problem)
    const float* Wih1 = (const float*)d_in[2];
    const float* Whh1 = (const float*)d_in[3];
    const float* bih1 = (const float*)d_in[4];
    const float* bhh1 = (const float*)d_in[5];
    const float* Wih2 = (const float*)d_in[6];
    const float* Whh2 = (const float*)d_in[7];
    const float* bih2 = (const float*)d_in[8];
    const float* bhh2 = (const float*)d_in[9];
    const float* Wlin = (const float*)d_in[10];
    const float* blin = (const float*)d_in[11];
    float* out = (float*)d_out;

    lstm_persistent<<<NBLK, NTHR>>>(x, Wih1, Whh1, bih1, bhh1,
                                    Wih2, Whh2, bih2, bhh2);

    linear_kernel<<<dim3((TT * BSZ) / 64, IND / 64), 128>>>(Wlin, blin, out);
}

// round 4
// speedup vs baseline: 1.2355x; 1.2355x over previous
#include <cuda_runtime.h>
#include <cstddef>

#define BSZ 256
#define TT  512
#define IND 128
#define HID 512
#define NBLK 128
#define NTHR 128

// ---------------- persistent device state (no cudaMalloc allowed) ----------
__device__ float g_zero[BSZ * HID];
__device__ float g_h1a[BSZ * HID];
__device__ float g_h1b[BSZ * HID];
__device__ float g_H2[(size_t)TT * BSZ * HID];   // h2 log [t][b][h]
__device__ unsigned g_cnt;                       // barrier arrive counter
__device__ volatile unsigned g_gen;              // barrier generation

// ---------------- packed f32x2 helpers -------------------------------------
__device__ __forceinline__ unsigned long long pack2(float x) {
    unsigned long long r;
    asm("mov.b64 %0, {%1, %1};" : "=l"(r) : "f"(x));
    return r;
}
__device__ __forceinline__ void fma2(unsigned long long& d,
                                     unsigned long long a,
                                     unsigned long long b) {
    asm("fma.rn.f32x2 %0, %1, %2, %0;" : "+l"(d) : "l"(a), "l"(b));
}
__device__ __forceinline__ float lo32(unsigned long long v) {
    return __uint_as_float((unsigned)v);
}
__device__ __forceinline__ float hi32(unsigned long long v) {
    return __uint_as_float((unsigned)(v >> 32));
}
__device__ __forceinline__ float sigm(float x) { return 1.0f / (1.0f + expf(-x)); }

// ---------------- grid-wide barrier (single wave: 128 blocks <= 148 SMs) ---
__device__ __forceinline__ void grid_sync() {
    __syncthreads();
    if (threadIdx.x == 0) {
        __threadfence();
        unsigned gen = g_gen;
        if (atomicAdd(&g_cnt, 1u) == NBLK - 1) {
            g_cnt = 0;
            __threadfence();
            g_gen = gen + 1;
        } else {
            while (g_gen == gen) __nanosleep(64);
            __threadfence();
        }
    }
    __syncthreads();
}

// ---------------- smem tile swizzle -----------------------------------------
// Tile stored k-major: logical (k, m) -> offset k*64 + (m ^ (k & 28)).
// Stores: within a warp, bank = (m ^ k4) & 31 covers all 32 banks (m: bits 0-1
// + warp bits, k4: bits 2-4) -> conflict-free STS.32.
// Loads: XOR touches only bits 2-4 of m, so 4-aligned groups stay contiguous
// and 16B-aligned -> LDS.128 stays legal and conflict-free.
__device__ __forceinline__ int swz(int k, int m) { return k * 64 + (m ^ (k & 28)); }

// ---------------- GEMM building blocks -------------------------------------
// Block tile: 64 rows (m) x 64 gate cols (n), K-tile = 32.
// Gate col n -> weight row (n>>4)*HID + j0 + (n&15).
struct Seg { const float* A; size_t lda; const float* W; size_t ldw; };

__device__ __forceinline__ void ldg_ab(const Seg& s, int j0, int koff, int tid,
                                       float4 (&ra)[4], float4 (&rb)[4]) {
#pragma unroll
    for (int i = 0; i < 4; i++) {
        int lin = tid + i * NTHR;
        int m = lin >> 3, k4 = (lin & 7) * 4;
        ra[i] = *(const float4*)(s.A + (size_t)m * s.lda + koff + k4);
        int wr = (m >> 4) * HID + j0 + (m & 15);
        rb[i] = *(const float4*)(s.W + (size_t)wr * s.ldw + koff + k4);
    }
}

__device__ __forceinline__ void sts_ab(float* As, float* Bs, int tid,
                                       const float4 (&ra)[4], const float4 (&rb)[4]) {
#pragma unroll
    for (int i = 0; i < 4; i++) {
        int lin = tid + i * NTHR;
        int m = lin >> 3, k4 = (lin & 7) * 4;
        int x = m ^ k4;                       // (k4+c) & 28 == k4 for c in 0..3
        As[(k4 + 0) * 64 + x] = ra[i].x;
        As[(k4 + 1) * 64 + x] = ra[i].y;
        As[(k4 + 2) * 64 + x] = ra[i].z;
        As[(k4 + 3) * 64 + x] = ra[i].w;
        Bs[(k4 + 0) * 64 + x] = rb[i].x;
        Bs[(k4 + 1) * 64 + x] = rb[i].y;
        Bs[(k4 + 2) * 64 + x] = rb[i].z;
        Bs[(k4 + 3) * 64 + x] = rb[i].w;
    }
}

// acc[mp][c] packs rows (tm*8+2mp, tm*8+2mp+1) for col tn*4+c.
__device__ __forceinline__ void mm_tile(const float* As, const float* Bs,
                                        int tm, int tn,
                                        unsigned long long (&acc)[4][4]) {
#pragma unroll
    for (int k = 0; k < 32; k++) {            // full unroll: swz() folds to consts
        ulonglong2 a01 = *(const ulonglong2*)(As + swz(k, tm * 8));
        ulonglong2 a23 = *(const ulonglong2*)(As + swz(k, tm * 8 + 4));
        float4 bv = *(const float4*)(Bs + swz(k, tn * 4));
        unsigned long long b0 = pack2(bv.x), b1 = pack2(bv.y),
                           b2 = pack2(bv.z), b3 = pack2(bv.w);
        fma2(acc[0][0], a01.x, b0); fma2(acc[0][1], a01.x, b1);
        fma2(acc[0][2], a01.x, b2); fma2(acc[0][3], a01.x, b3);
        fma2(acc[1][0], a01.y, b0); fma2(acc[1][1], a01.y, b1);
        fma2(acc[1][2], a01.y, b2); fma2(acc[1][3], a01.y, b3);
        fma2(acc[2][0], a23.x, b0); fma2(acc[2][1], a23.x, b1);
        fma2(acc[2][2], a23.x, b2); fma2(acc[2][3], a23.x, b3);
        fma2(acc[3][0], a23.y, b0); fma2(acc[3][1], a23.y, b1);
        fma2(acc[3][2], a23.y, b2); fma2(acc[3][3], a23.y, b3);
    }
}

// Double-buffered two-segment GEMM: gates += A0@W0^T (nt0 tiles) + A1@W1^T (nt1 tiles)
__device__ __forceinline__ void gates_gemm(const Seg& s0, int nt0,
                                           const Seg& s1, int nt1,
                                           float* pool, int j0, int tid,
                                           int tm, int tn,
                                           unsigned long long (&acc)[4][4]) {
    float* As0 = pool;          float* As1 = pool + 2048;
    float* Bs0 = pool + 4096;   float* Bs1 = pool + 6144;
#pragma unroll
    for (int i = 0; i < 4; i++)
#pragma unroll
        for (int j = 0; j < 4; j++) acc[i][j] = 0ull;

    const int total = nt0 + nt1;
    float4 ra[4], rb[4];
    ldg_ab(s0, j0, 0, tid, ra, rb);
    sts_ab(As0, Bs0, tid, ra, rb);
    __syncthreads();

#pragma unroll 1
    for (int kt = 0; kt < total; kt++) {
        const int nxt = kt + 1;
        const bool has = nxt < total;
        if (has) {
            if (nxt < nt0) ldg_ab(s0, j0, nxt * 32, tid, ra, rb);
            else           ldg_ab(s1, j0, (nxt - nt0) * 32, tid, ra, rb);
        }
        const float* Ac = (kt & 1) ? As1 : As0;
        const float* Bc = (kt & 1) ? Bs1 : Bs0;
        mm_tile(Ac, Bc, tm, tn, acc);
        if (has) {
            float* An = (nxt & 1) ? As1 : As0;
            float* Bn = (nxt & 1) ? Bs1 : Bs0;
            sts_ab(An, Bn, tid, ra, rb);
        }
        __syncthreads();
    }
}

__device__ __forceinline__ void acc_to_cs(float* Cs,
                                          const unsigned long long (&acc)[4][4],
                                          int tm, int tn) {
#pragma unroll
    for (int mp = 0; mp < 4; mp++)
#pragma unroll
        for (int c = 0; c < 4; c++) {
            int n = tn * 4 + c;
            int m = tm * 8 + mp * 2;
            Cs[n * 65 + m]     = lo32(acc[mp][c]);
            Cs[n * 65 + m + 1] = hi32(acc[mp][c]);
        }
}

__device__ __forceinline__ void cell_update(const float* Cs, const float* bs,
                                            float (&cr)[8], float* hglob,
                                            int m0, int j0, int tid) {
#pragma unroll
    for (int w = 0; w < 8; w++) {
        int item = w * NTHR + tid;
        int jj = item & 15;
        int mm = item >> 4;
        float gi = Cs[(jj)      * 65 + mm] + bs[jj];
        float gf = Cs[(16 + jj) * 65 + mm] + bs[16 + jj];
        float gg = Cs[(32 + jj) * 65 + mm] + bs[32 + jj];
        float go = Cs[(48 + jj) * 65 + mm] + bs[48 + jj];
        float iv = sigm(gi), fv = sigm(gf);
        float gv = tanhf(gg), ov = sigm(go);
        float cn = fv * cr[w] + iv * gv;
        cr[w] = cn;
        hglob[(size_t)(m0 + mm) * HID + j0 + jj] = ov * tanhf(cn);
    }
}

// ============================================================================
// Persistent LSTM kernel: whole T=512 recurrence, 128 blocks, 1 launch.
// Block -> (m0 = (bid>>5)*64 batch rows, j0 = (bid&31)*16 hidden units).
// ============================================================================
__global__ __launch_bounds__(NTHR, 1) void lstm_persistent(
    const float* __restrict__ x,
    const float* __restrict__ Wih1, const float* __restrict__ Whh1,
    const float* __restrict__ bih1, const float* __restrict__ bhh1,
    const float* __restrict__ Wih2, const float* __restrict__ Whh2,
    const float* __restrict__ bih2, const float* __restrict__ bhh2)
{
    __shared__ __align__(16) float pool[8192];   // As0|As1|Bs0|Bs1 ; Cs aliases pool
    __shared__ float bs1[64], bs2[64];
    float* Cs = pool;                            // 64*65 floats, used post-GEMM

    const int tid = threadIdx.x;
    const int bid = blockIdx.x;
    const int m0 = (bid >> 5) * 64;
    const int j0 = (bid & 31) * 16;
    const int tm = tid & 7;
    const int tn = tid >> 3;

    // zero the t=0 state buffer
    {
        int base = (bid * NTHR + tid) * 8;
#pragma unroll
        for (int i = 0; i < 8; i++) g_zero[base + i] = 0.0f;
    }
    // bias sums for this block's 64 gate-columns (index n = gate*16 + jj)
    if (tid < 64) {
        int wr = (tid >> 4) * HID + j0 + (tid & 15);
        bs1[tid] = bih1[wr] + bhh1[wr];
        bs2[tid] = bih2[wr] + bhh2[wr];
    }
    grid_sync();

    float c1r[8], c2r[8];
#pragma unroll
    for (int i = 0; i < 8; i++) { c1r[i] = 0.0f; c2r[i] = 0.0f; }

    unsigned long long acc[4][4];

#pragma unroll 1
    for (int t = 0; t < TT; t++) {
        const float* h1p = (t == 0) ? g_zero : ((t & 1) ? g_h1a : g_h1b);
        float*       h1c = (t & 1) ? g_h1b : g_h1a;

        // ---- layer 1: gates = x_t @ Wih1^T + h1prev @ Whh1^T --------------
        Seg s0 { x + (size_t)m0 * (TT * IND) + (size_t)t * IND, (size_t)(TT * IND), Wih1, IND };
        Seg s1 { h1p + (size_t)m0 * HID, HID, Whh1, HID };
        gates_gemm(s0, IND / 32, s1, HID / 32, pool, j0, tid, tm, tn, acc);
        acc_to_cs(Cs, acc, tm, tn);
        __syncthreads();
        cell_update(Cs, bs1, c1r, h1c, m0, j0, tid);
        grid_sync();                                   // h1(t) visible chip-wide

        // ---- layer 2: gates = h1(t) @ Wih2^T + h2(t-1) @ Whh2^T -----------
        const float* h2p = (t == 0) ? g_zero : (g_H2 + (size_t)(t - 1) * BSZ * HID);
        float*       h2c = g_H2 + (size_t)t * BSZ * HID;
        Seg s2 { h1c + (size_t)m0 * HID, HID, Wih2, HID };
        Seg s3 { h2p + (size_t)m0 * HID, HID, Whh2, HID };
        gates_gemm(s2, HID / 32, s3, HID / 32, pool, j0, tid, tm, tn, acc);
        acc_to_cs(Cs, acc, tm, tn);
        __syncthreads();
        cell_update(Cs, bs2, c2r, h2c, m0, j0, tid);
        grid_sync();                                   // h2(t) visible chip-wide
    }
}

// ============================================================================
// Output linear: out[b,t,:] = H2[t,b,:] @ Wlin^T + blin
// M = T*B = 131072 (row r = t*256+b), N = 128, K = 512. Fully parallel.
// ============================================================================
__global__ __launch_bounds__(128, 2) void linear_kernel(
    const float* __restrict__ Wl, const float* __restrict__ bl,
    float* __restrict__ out)
{
    __shared__ __align__(16) float smem[4096];
    float* As = smem;
    float* Bs = smem + 2048;

    const int tid = threadIdx.x;
    const int r0  = blockIdx.x * 64;
    const int n0  = blockIdx.y * 64;
    const int tm  = tid & 7;
    const int tn  = tid >> 3;
    const float* H2 = g_H2;

    unsigned long long acc[4][4];
#pragma unroll
    for (int i = 0; i < 4; i++)
#pragma unroll
        for (int j = 0; j < 4; j++) acc[i][j] = 0ull;

#pragma unroll 1
    for (int k0 = 0; k0 < HID; k0 += 32) {
        __syncthreads();
#pragma unroll
        for (int i = 0; i < 4; i++) {
            int lin = tid + i * 128;
            int m = lin >> 3, k4 = (lin & 7) * 4;
            int xsw = m ^ k4;
            float4 v = *(const float4*)(H2 + (size_t)(r0 + m) * HID + k0 + k4);
            As[(k4 + 0) * 64 + xsw] = v.x;
            As[(k4 + 1) * 64 + xsw] = v.y;
            As[(k4 + 2) * 64 + xsw] = v.z;
            As[(k4 + 3) * 64 + xsw] = v.w;
            float4 w = *(const float4*)(Wl + (size_t)(n0 + m) * HID + k0 + k4);
            Bs[(k4 + 0) * 64 + xsw] = w.x;
            Bs[(k4 + 1) * 64 + xsw] = w.y;
            Bs[(k4 + 2) * 64 + xsw] = w.z;
            Bs[(k4 + 3) * 64 + xsw] = w.w;
        }
        __syncthreads();
        mm_tile(As, Bs, tm, tn, acc);
    }

#pragma unroll
    for (int mp = 0; mp < 4; mp++) {
#pragma unroll
        for (int half = 0; half < 2; half++) {
            int r = r0 + tm * 8 + mp * 2 + half;
            int t = r >> 8;
            int b = r & 255;
            float* orow = out + (size_t)b * TT * IND + (size_t)t * IND;
#pragma unroll
            for (int c = 0; c < 4; c++) {
                int col = n0 + tn * 4 + c;
                float v = half ? hi32(acc[mp][c]) : lo32(acc[mp][c]);
                orow[col] = v + bl[col];
            }
        }
    }
}

extern "C" void kernel_launch(void* const* d_in, const int* in_sizes, int n_in,
                              void* d_out, int out_size)
{
    const float* x    = (const float*)d_in[0];
    // d_in[1] = future (0 for this problem)
    const float* Wih1 = (const float*)d_in[2];
    const float* Whh1 = (const float*)d_in[3];
    const float* bih1 = (const float*)d_in[4];
    const float* bhh1 = (const float*)d_in[5];
    const float* Wih2 = (const float*)d_in[6];
    const float* Whh2 = (const float*)d_in[7];
    const float* bih2 = (const float*)d_in[8];
    const float* bhh2 = (const float*)d_in[9];
    const float* Wlin = (const float*)d_in[10];
    const float* blin = (const float*)d_in[11];
    float* out = (float*)d_out;

    lstm_persistent<<<NBLK, NTHR>>>(x, Wih1, Whh1, bih1, bhh1,
                                    Wih2, Whh2, bih2, bhh2);

    linear_kernel<<<dim3((TT * BSZ) / 64, IND / 64), 128>>>(Wlin, blin, out);
}

// round 5
// speedup vs baseline: 1.6178x; 1.3094x over previous
#include <cuda_runtime.h>
#include <cstddef>

#define BSZ 256
#define TT  512
#define IND 128
#define HID 512
#define NBLK 128
#define NTHR 256
#define CHUNK_BLKS 32     // blocks per m-chunk (independent barrier group)

// ---------------- persistent device state (no cudaMalloc allowed) ----------
__device__ float g_zero[BSZ * HID];
__device__ float g_h1a[BSZ * HID];
__device__ float g_h1b[BSZ * HID];
__device__ float g_H2[(size_t)TT * BSZ * HID];   // h2 log [t][b][h]
__device__ unsigned g_cnt4[4 * 32];              // per-chunk arrive counters (padded)
__device__ volatile unsigned g_gen4[4 * 32];     // per-chunk generations (padded)

// ---------------- packed f32x2 helpers -------------------------------------
__device__ __forceinline__ unsigned long long pack2(float x) {
    unsigned long long r;
    asm("mov.b64 %0, {%1, %1};" : "=l"(r) : "f"(x));
    return r;
}
__device__ __forceinline__ void fma2(unsigned long long& d,
                                     unsigned long long a,
                                     unsigned long long b) {
    asm("fma.rn.f32x2 %0, %1, %2, %0;" : "+l"(d) : "l"(a), "l"(b));
}
__device__ __forceinline__ float lo32(unsigned long long v) {
    return __uint_as_float((unsigned)v);
}
__device__ __forceinline__ float hi32(unsigned long long v) {
    return __uint_as_float((unsigned)(v >> 32));
}
__device__ __forceinline__ float sigm(float x) { return 1.0f / (1.0f + expf(-x)); }

// ---------------- per-m-chunk barrier (32 blocks each, all resident) -------
__device__ __forceinline__ void chunk_sync(int mc) {
    __syncthreads();
    if (threadIdx.x == 0) {
        __threadfence();
        unsigned* cnt = &g_cnt4[mc * 32];
        volatile unsigned* gen = &g_gen4[mc * 32];
        unsigned g = *gen;
        if (atomicAdd(cnt, 1u) == CHUNK_BLKS - 1) {
            *cnt = 0;
            __threadfence();
            *gen = g + 1;
        } else {
            while (*gen == g) __nanosleep(32);
            __threadfence();
        }
    }
    __syncthreads();
}

// ---------------- smem tile swizzle -----------------------------------------
// (k, m) -> k*64 + (m ^ (k & 28)). Conflict-free STS.32 and LDS.128 (16B groups
// stay aligned; XOR only touches bits 2-4 of m).
__device__ __forceinline__ int swz(int k, int m) { return k * 64 + (m ^ (k & 28)); }

// ---------------- GEMM building blocks -------------------------------------
// Block tile: 64 rows (m) x 64 gate cols (n), K-tile = 32, 256 threads.
// Thread tile 4m x 4n: tm = tid & 15 (rows tm*4..+3), tn = tid >> 4 (cols tn*4..+3).
// Gate col n -> weight row (n>>4)*HID + j0 + (n&15).
struct Seg { const float* A; size_t lda; const float* W; size_t ldw; };

__device__ __forceinline__ void ldg_ab(const Seg& s, int j0, int koff, int tid,
                                       float4 (&ra)[2], float4 (&rb)[2]) {
#pragma unroll
    for (int i = 0; i < 2; i++) {
        int lin = tid + i * NTHR;
        int m = lin >> 3, k4 = (lin & 7) * 4;
        ra[i] = *(const float4*)(s.A + (size_t)m * s.lda + koff + k4);
        int wr = (m >> 4) * HID + j0 + (m & 15);
        rb[i] = *(const float4*)(s.W + (size_t)wr * s.ldw + koff + k4);
    }
}

__device__ __forceinline__ void sts_ab(float* As, float* Bs, int tid,
                                       const float4 (&ra)[2], const float4 (&rb)[2]) {
#pragma unroll
    for (int i = 0; i < 2; i++) {
        int lin = tid + i * NTHR;
        int m = lin >> 3, k4 = (lin & 7) * 4;
        int x = m ^ k4;                       // (k4+c) & 28 == k4 for c in 0..3
        As[(k4 + 0) * 64 + x] = ra[i].x;
        As[(k4 + 1) * 64 + x] = ra[i].y;
        As[(k4 + 2) * 64 + x] = ra[i].z;
        As[(k4 + 3) * 64 + x] = ra[i].w;
        Bs[(k4 + 0) * 64 + x] = rb[i].x;
        Bs[(k4 + 1) * 64 + x] = rb[i].y;
        Bs[(k4 + 2) * 64 + x] = rb[i].z;
        Bs[(k4 + 3) * 64 + x] = rb[i].w;
    }
}

// acc[mp][c]: rows (tm*4 + 2mp, +1), col tn*4 + c, rows packed in f32x2.
__device__ __forceinline__ void mm_tile(const float* As, const float* Bs,
                                        int tm, int tn,
                                        unsigned long long (&acc)[2][4]) {
#pragma unroll
    for (int k = 0; k < 32; k++) {            // full unroll: swz() folds per-k
        ulonglong2 a = *(const ulonglong2*)(As + swz(k, tm * 4));
        float4 bv = *(const float4*)(Bs + swz(k, tn * 4));
        unsigned long long b0 = pack2(bv.x), b1 = pack2(bv.y),
                           b2 = pack2(bv.z), b3 = pack2(bv.w);
        fma2(acc[0][0], a.x, b0); fma2(acc[0][1], a.x, b1);
        fma2(acc[0][2], a.x, b2); fma2(acc[0][3], a.x, b3);
        fma2(acc[1][0], a.y, b0); fma2(acc[1][1], a.y, b1);
        fma2(acc[1][2], a.y, b2); fma2(acc[1][3], a.y, b3);
    }
}

// Double-buffered two-segment GEMM: gates += A0@W0^T (nt0 tiles) + A1@W1^T (nt1)
__device__ __forceinline__ void gates_gemm(const Seg& s0, int nt0,
                                           const Seg& s1, int nt1,
                                           float* pool, int j0, int tid,
                                           int tm, int tn,
                                           unsigned long long (&acc)[2][4]) {
    float* As0 = pool;          float* As1 = pool + 2048;
    float* Bs0 = pool + 4096;   float* Bs1 = pool + 6144;
#pragma unroll
    for (int i = 0; i < 2; i++)
#pragma unroll
        for (int j = 0; j < 4; j++) acc[i][j] = 0ull;

    const int total = nt0 + nt1;
    float4 ra[2], rb[2];
    ldg_ab(s0, j0, 0, tid, ra, rb);
    sts_ab(As0, Bs0, tid, ra, rb);
    __syncthreads();

#pragma unroll 1
    for (int kt = 0; kt < total; kt++) {
        const int nxt = kt + 1;
        const bool has = nxt < total;
        if (has) {
            if (nxt < nt0) ldg_ab(s0, j0, nxt * 32, tid, ra, rb);
            else           ldg_ab(s1, j0, (nxt - nt0) * 32, tid, ra, rb);
        }
        const float* Ac = (kt & 1) ? As1 : As0;
        const float* Bc = (kt & 1) ? Bs1 : Bs0;
        mm_tile(Ac, Bc, tm, tn, acc);
        if (has) {
            float* An = (nxt & 1) ? As1 : As0;
            float* Bn = (nxt & 1) ? Bs1 : Bs0;
            sts_ab(An, Bn, tid, ra, rb);
        }
        __syncthreads();
    }
}

__device__ __forceinline__ void acc_to_cs(float* Cs,
                                          const unsigned long long (&acc)[2][4],
                                          int tm, int tn) {
#pragma unroll
    for (int mp = 0; mp < 2; mp++)
#pragma unroll
        for (int c = 0; c < 4; c++) {
            int n = tn * 4 + c;
            int m = tm * 4 + mp * 2;
            Cs[n * 65 + m]     = lo32(acc[mp][c]);
            Cs[n * 65 + m + 1] = hi32(acc[mp][c]);
        }
}

// 1024 cell items (64 m x 16 jj), 256 threads -> 4 each. cr[4] = c-state regs.
__device__ __forceinline__ void cell_update(const float* Cs, const float* bs,
                                            float (&cr)[4], float* hglob,
                                            int m0, int j0, int tid) {
#pragma unroll
    for (int w = 0; w < 4; w++) {
        int item = w * NTHR + tid;
        int jj = item & 15;
        int mm = item >> 4;
        float gi = Cs[(jj)      * 65 + mm] + bs[jj];
        float gf = Cs[(16 + jj) * 65 + mm] + bs[16 + jj];
        float gg = Cs[(32 + jj) * 65 + mm] + bs[32 + jj];
        float go = Cs[(48 + jj) * 65 + mm] + bs[48 + jj];
        float iv = sigm(gi), fv = sigm(gf);
        float gv = tanhf(gg), ov = sigm(go);
        float cn = fv * cr[w] + iv * gv;
        cr[w] = cn;
        hglob[(size_t)(m0 + mm) * HID + j0 + jj] = ov * tanhf(cn);
    }
}

// ============================================================================
// Persistent LSTM kernel: whole T=512 recurrence, 128 blocks x 256 threads.
// Block -> m-chunk mc = bid>>5 (m0 = mc*64), j-chunk (bid&31)*16.
// m-chunks are data-independent: barriers are per-chunk (32 blocks).
// ============================================================================
__global__ __launch_bounds__(NTHR, 1) void lstm_persistent(
    const float* __restrict__ x,
    const float* __restrict__ Wih1, const float* __restrict__ Whh1,
    const float* __restrict__ bih1, const float* __restrict__ bhh1,
    const float* __restrict__ Wih2, const float* __restrict__ Whh2,
    const float* __restrict__ bih2, const float* __restrict__ bhh2)
{
    __shared__ __align__(16) float pool[8192];   // As0|As1|Bs0|Bs1 ; Cs aliases pool
    __shared__ float bs1[64], bs2[64];
    float* Cs = pool;

    const int tid = threadIdx.x;
    const int bid = blockIdx.x;
    const int mc  = bid >> 5;
    const int m0  = mc * 64;
    const int j0  = (bid & 31) * 16;
    const int tm  = tid & 15;
    const int tn  = tid >> 4;

    // zero this chunk's rows of the t=0 state buffer
    {
        int jc = bid & 31;                       // each block zeroes 2 rows
        int row = m0 + jc * 2;
        float* dst = g_zero + (size_t)row * HID;
#pragma unroll
        for (int i = 0; i < 4; i++) dst[tid + i * NTHR] = 0.0f;
    }
    // bias sums for this block's 64 gate-columns (index n = gate*16 + jj)
    if (tid < 64) {
        int wr = (tid >> 4) * HID + j0 + (tid & 15);
        bs1[tid] = bih1[wr] + bhh1[wr];
        bs2[tid] = bih2[wr] + bhh2[wr];
    }
    chunk_sync(mc);

    float c1r[4], c2r[4];
#pragma unroll
    for (int i = 0; i < 4; i++) { c1r[i] = 0.0f; c2r[i] = 0.0f; }

    unsigned long long acc[2][4];

#pragma unroll 1
    for (int t = 0; t < TT; t++) {
        const float* h1p = (t == 0) ? g_zero : ((t & 1) ? g_h1a : g_h1b);
        float*       h1c = (t & 1) ? g_h1b : g_h1a;

        // ---- layer 1: gates = x_t @ Wih1^T + h1prev @ Whh1^T --------------
        Seg s0 { x + (size_t)m0 * (TT * IND) + (size_t)t * IND, (size_t)(TT * IND), Wih1, IND };
        Seg s1 { h1p + (size_t)m0 * HID, HID, Whh1, HID };
        gates_gemm(s0, IND / 32, s1, HID / 32, pool, j0, tid, tm, tn, acc);
        acc_to_cs(Cs, acc, tm, tn);
        __syncthreads();
        cell_update(Cs, bs1, c1r, h1c, m0, j0, tid);
        chunk_sync(mc);                                // h1(t) visible chunk-wide

        // ---- layer 2: gates = h1(t) @ Wih2^T + h2(t-1) @ Whh2^T -----------
        const float* h2p = (t == 0) ? g_zero : (g_H2 + (size_t)(t - 1) * BSZ * HID);
        float*       h2c = g_H2 + (size_t)t * BSZ * HID;
        Seg s2 { h1c + (size_t)m0 * HID, HID, Wih2, HID };
        Seg s3 { h2p + (size_t)m0 * HID, HID, Whh2, HID };
        gates_gemm(s2, HID / 32, s3, HID / 32, pool, j0, tid, tm, tn, acc);
        acc_to_cs(Cs, acc, tm, tn);
        __syncthreads();
        cell_update(Cs, bs2, c2r, h2c, m0, j0, tid);
        chunk_sync(mc);                                // h2(t) visible chunk-wide
    }
}

// ============================================================================
// Output linear: out[b,t,:] = H2[t,b,:] @ Wlin^T + blin
// M = T*B = 131072 (row r = t*256+b), N = 128, K = 512. Fully parallel.
// ============================================================================
__global__ __launch_bounds__(NTHR, 1) void linear_kernel(
    const float* __restrict__ Wl, const float* __restrict__ bl,
    float* __restrict__ out)
{
    __shared__ __align__(16) float smem[4096];
    float* As = smem;
    float* Bs = smem + 2048;

    const int tid = threadIdx.x;
    const int r0  = blockIdx.x * 64;
    const int n0  = blockIdx.y * 64;
    const int tm  = tid & 15;
    const int tn  = tid >> 4;
    const float* H2 = g_H2;

    unsigned long long acc[2][4];
#pragma unroll
    for (int i = 0; i < 2; i++)
#pragma unroll
        for (int j = 0; j < 4; j++) acc[i][j] = 0ull;

#pragma unroll 1
    for (int k0 = 0; k0 < HID; k0 += 32) {
        __syncthreads();
#pragma unroll
        for (int i = 0; i < 2; i++) {
            int lin = tid + i * NTHR;
            int m = lin >> 3, k4 = (lin & 7) * 4;
            int xsw = m ^ k4;
            float4 v = *(const float4*)(H2 + (size_t)(r0 + m) * HID + k0 + k4);
            As[(k4 + 0) * 64 + xsw] = v.x;
            As[(k4 + 1) * 64 + xsw] = v.y;
            As[(k4 + 2) * 64 + xsw] = v.z;
            As[(k4 + 3) * 64 + xsw] = v.w;
            float4 w = *(const float4*)(Wl + (size_t)(n0 + m) * HID + k0 + k4);
            Bs[(k4 + 0) * 64 + xsw] = w.x;
            Bs[(k4 + 1) * 64 + xsw] = w.y;
            Bs[(k4 + 2) * 64 + xsw] = w.z;
            Bs[(k4 + 3) * 64 + xsw] = w.w;
        }
        __syncthreads();
        mm_tile(As, Bs, tm, tn, acc);
    }

#pragma unroll
    for (int mp = 0; mp < 2; mp++) {
#pragma unroll
        for (int half = 0; half < 2; half++) {
            int r = r0 + tm * 4 + mp * 2 + half;
            int t = r >> 8;
            int b = r & 255;
            float* orow = out + (size_t)b * TT * IND + (size_t)t * IND;
#pragma unroll
            for (int c = 0; c < 4; c++) {
                int col = n0 + tn * 4 + c;
                float v = half ? hi32(acc[mp][c]) : lo32(acc[mp][c]);
                orow[col] = v + bl[col];
            }
        }
    }
}

extern "C" void kernel_launch(void* const* d_in, const int* in_sizes, int n_in,
                              void* d_out, int out_size)
{
    const float* x    = (const float*)d_in[0];
    // d_in[1] = future (0 for this problem)
    const float* Wih1 = (const float*)d_in[2];
    const float* Whh1 = (const float*)d_in[3];
    const float* bih1 = (const float*)d_in[4];
    const float* bhh1 = (const float*)d_in[5];
    const float* Wih2 = (const float*)d_in[6];
    const float* Whh2 = (const float*)d_in[7];
    const float* bih2 = (const float*)d_in[8];
    const float* bhh2 = (const float*)d_in[9];
    const float* Wlin = (const float*)d_in[10];
    const float* blin = (const float*)d_in[11];
    float* out = (float*)d_out;

    lstm_persistent<<<NBLK, NTHR>>>(x, Wih1, Whh1, bih1, bhh1,
                                    Wih2, Whh2, bih2, bhh2);

    linear_kernel<<<dim3((TT * BSZ) / 64, IND / 64), NTHR>>>(Wlin, blin, out);
}

// round 6
// speedup vs baseline: 1.6263x; 1.0053x over previous
#include <cuda_runtime.h>
#include <cstddef>

#define BSZ 256
#define TT  512
#define IND 128
#define HID 512
#define NBLK 128
#define NTHR 256
#define CHUNK_BLKS 32     // blocks per m-chunk (independent barrier group)

// ---------------- persistent device state (no cudaMalloc allowed) ----------
__device__ float g_zero[BSZ * HID];
__device__ float g_h1a[BSZ * HID];
__device__ float g_h1b[BSZ * HID];
__device__ float g_H2[(size_t)TT * BSZ * HID];   // h2 log [t][b][h]
__device__ unsigned g_cnt4[4 * 32];              // per-chunk arrive counters (padded)
__device__ volatile unsigned g_gen4[4 * 32];     // per-chunk generations (padded)

// ---------------- packed f32x2 helpers -------------------------------------
__device__ __forceinline__ unsigned long long pack2(float x) {
    unsigned long long r;
    asm("mov.b64 %0, {%1, %1};" : "=l"(r) : "f"(x));
    return r;
}
__device__ __forceinline__ void fma2(unsigned long long& d,
                                     unsigned long long a,
                                     unsigned long long b) {
    asm("fma.rn.f32x2 %0, %1, %2, %0;" : "+l"(d) : "l"(a), "l"(b));
}
__device__ __forceinline__ float lo32(unsigned long long v) {
    return __uint_as_float((unsigned)v);
}
__device__ __forceinline__ float hi32(unsigned long long v) {
    return __uint_as_float((unsigned)(v >> 32));
}
__device__ __forceinline__ float sigm(float x) { return 1.0f / (1.0f + expf(-x)); }

// ---------------- per-m-chunk barrier (32 blocks each, all resident) -------
__device__ __forceinline__ void chunk_sync(int mc) {
    __syncthreads();
    if (threadIdx.x == 0) {
        __threadfence();
        unsigned* cnt = &g_cnt4[mc * 32];
        volatile unsigned* gen = &g_gen4[mc * 32];
        unsigned g = *gen;
        if (atomicAdd(cnt, 1u) == CHUNK_BLKS - 1) {
            *cnt = 0;
            __threadfence();
            *gen = g + 1;
        } else {
            while (*gen == g) __nanosleep(32);
            __threadfence();
        }
    }
    __syncthreads();
}

// ---------------- smem tile swizzle -----------------------------------------
// (k, m) -> k*64 + (m ^ (k & 28)). Conflict-free STS.32 and LDS.128 (16B groups
// stay aligned; XOR only touches bits 2-4 of m).
__device__ __forceinline__ int swz(int k, int m) { return k * 64 + (m ^ (k & 28)); }

// ---------------- GEMM building blocks -------------------------------------
// Block tile: 64 rows (m) x 64 gate cols (n), K-tile = 32, 256 threads = 8 warps.
// 2-D warp layout: warp w -> (wm = w&1)*32 m-rows, (wn = w>>1)*16 n-cols.
// Lane -> (lm = lane&7)*4 rows, (ln = lane>>3)*4 cols within warp footprint.
// Per warp per k: A touch = 32 rows = 128B = 1 wavefront; B = 16 cols = 64B = 1 wf.
// Gate col n -> weight row (n>>4)*HID + j0 + (n&15).
struct Seg { const float* A; size_t lda; const float* W; size_t ldw; };

__device__ __forceinline__ void ldg_ab(const Seg& s, int j0, int koff, int tid,
                                       float4 (&ra)[2], float4 (&rb)[2]) {
#pragma unroll
    for (int i = 0; i < 2; i++) {
        int lin = tid + i * NTHR;
        int m = lin >> 3, k4 = (lin & 7) * 4;
        ra[i] = *(const float4*)(s.A + (size_t)m * s.lda + koff + k4);
        int wr = (m >> 4) * HID + j0 + (m & 15);
        rb[i] = *(const float4*)(s.W + (size_t)wr * s.ldw + koff + k4);
    }
}

__device__ __forceinline__ void sts_ab(float* As, float* Bs, int tid,
                                       const float4 (&ra)[2], const float4 (&rb)[2]) {
#pragma unroll
    for (int i = 0; i < 2; i++) {
        int lin = tid + i * NTHR;
        int m = lin >> 3, k4 = (lin & 7) * 4;
        int x = m ^ k4;                       // (k4+c) & 28 == k4 for c in 0..3
        As[(k4 + 0) * 64 + x] = ra[i].x;
        As[(k4 + 1) * 64 + x] = ra[i].y;
        As[(k4 + 2) * 64 + x] = ra[i].z;
        As[(k4 + 3) * 64 + x] = ra[i].w;
        Bs[(k4 + 0) * 64 + x] = rb[i].x;
        Bs[(k4 + 1) * 64 + x] = rb[i].y;
        Bs[(k4 + 2) * 64 + x] = rb[i].z;
        Bs[(k4 + 3) * 64 + x] = rb[i].w;
    }
}

// acc[mp][c]: rows (am + 2mp, +1) packed in f32x2, col an + c.
__device__ __forceinline__ void mm_tile(const float* As, const float* Bs,
                                        int am, int an,
                                        unsigned long long (&acc)[2][4]) {
#pragma unroll
    for (int k = 0; k < 32; k++) {            // full unroll: swz() folds per-k
        ulonglong2 a = *(const ulonglong2*)(As + swz(k, am));
        float4 bv = *(const float4*)(Bs + swz(k, an));
        unsigned long long b0 = pack2(bv.x), b1 = pack2(bv.y),
                           b2 = pack2(bv.z), b3 = pack2(bv.w);
        fma2(acc[0][0], a.x, b0); fma2(acc[0][1], a.x, b1);
        fma2(acc[0][2], a.x, b2); fma2(acc[0][3], a.x, b3);
        fma2(acc[1][0], a.y, b0); fma2(acc[1][1], a.y, b1);
        fma2(acc[1][2], a.y, b2); fma2(acc[1][3], a.y, b3);
    }
}

// Double-buffered two-segment GEMM: gates += A0@W0^T (nt0 tiles) + A1@W1^T (nt1)
__device__ __forceinline__ void gates_gemm(const Seg& s0, int nt0,
                                           const Seg& s1, int nt1,
                                           float* pool, int j0, int tid,
                                           int am, int an,
                                           unsigned long long (&acc)[2][4]) {
    float* As0 = pool;          float* As1 = pool + 2048;
    float* Bs0 = pool + 4096;   float* Bs1 = pool + 6144;
#pragma unroll
    for (int i = 0; i < 2; i++)
#pragma unroll
        for (int j = 0; j < 4; j++) acc[i][j] = 0ull;

    const int total = nt0 + nt1;
    float4 ra[2], rb[2];
    ldg_ab(s0, j0, 0, tid, ra, rb);
    sts_ab(As0, Bs0, tid, ra, rb);
    __syncthreads();

#pragma unroll 1
    for (int kt = 0; kt < total; kt++) {
        const int nxt = kt + 1;
        const bool has = nxt < total;
        if (has) {
            if (nxt < nt0) ldg_ab(s0, j0, nxt * 32, tid, ra, rb);
            else           ldg_ab(s1, j0, (nxt - nt0) * 32, tid, ra, rb);
        }
        const float* Ac = (kt & 1) ? As1 : As0;
        const float* Bc = (kt & 1) ? Bs1 : Bs0;
        mm_tile(Ac, Bc, am, an, acc);
        if (has) {
            float* An = (nxt & 1) ? As1 : As0;
            float* Bn = (nxt & 1) ? Bs1 : Bs0;
            sts_ab(An, Bn, tid, ra, rb);
        }
        __syncthreads();
    }
}

__device__ __forceinline__ void acc_to_cs(float* Cs,
                                          const unsigned long long (&acc)[2][4],
                                          int am, int an) {
#pragma unroll
    for (int mp = 0; mp < 2; mp++)
#pragma unroll
        for (int c = 0; c < 4; c++) {
            int n = an + c;
            int m = am + mp * 2;
            Cs[n * 65 + m]     = lo32(acc[mp][c]);
            Cs[n * 65 + m + 1] = hi32(acc[mp][c]);
        }
}

// 1024 cell items (64 m x 16 jj), 256 threads -> 4 each. cr[4] = c-state regs.
__device__ __forceinline__ void cell_update(const float* Cs, const float* bs,
                                            float (&cr)[4], float* hglob,
                                            int m0, int j0, int tid) {
#pragma unroll
    for (int w = 0; w < 4; w++) {
        int item = w * NTHR + tid;
        int jj = item & 15;
        int mm = item >> 4;
        float gi = Cs[(jj)      * 65 + mm] + bs[jj];
        float gf = Cs[(16 + jj) * 65 + mm] + bs[16 + jj];
        float gg = Cs[(32 + jj) * 65 + mm] + bs[32 + jj];
        float go = Cs[(48 + jj) * 65 + mm] + bs[48 + jj];
        float iv = sigm(gi), fv = sigm(gf);
        float gv = tanhf(gg), ov = sigm(go);
        float cn = fv * cr[w] + iv * gv;
        cr[w] = cn;
        hglob[(size_t)(m0 + mm) * HID + j0 + jj] = ov * tanhf(cn);
    }
}

// ============================================================================
// Persistent LSTM kernel: whole T=512 recurrence, 128 blocks x 256 threads.
// Block -> m-chunk mc = bid>>5 (m0 = mc*64), j-chunk (bid&31)*16.
// m-chunks are data-independent: barriers are per-chunk (32 blocks).
// ============================================================================
__global__ __launch_bounds__(NTHR, 1) void lstm_persistent(
    const float* __restrict__ x,
    const float* __restrict__ Wih1, const float* __restrict__ Whh1,
    const float* __restrict__ bih1, const float* __restrict__ bhh1,
    const float* __restrict__ Wih2, const float* __restrict__ Whh2,
    const float* __restrict__ bih2, const float* __restrict__ bhh2)
{
    __shared__ __align__(16) float pool[8192];   // As0|As1|Bs0|Bs1 ; Cs aliases pool
    __shared__ float bs1[64], bs2[64];
    float* Cs = pool;

    const int tid  = threadIdx.x;
    const int bid  = blockIdx.x;
    const int mc   = bid >> 5;
    const int m0   = mc * 64;
    const int j0   = (bid & 31) * 16;
    const int lane = tid & 31;
    const int warp = tid >> 5;
    const int am   = (warp & 1) * 32 + (lane & 7) * 4;   // 4 m-rows
    const int an   = (warp >> 1) * 16 + (lane >> 3) * 4; // 4 n-cols

    // zero this chunk's rows of the t=0 state buffer
    {
        int jc = bid & 31;                       // each block zeroes 2 rows
        int row = m0 + jc * 2;
        float* dst = g_zero + (size_t)row * HID;
#pragma unroll
        for (int i = 0; i < 4; i++) dst[tid + i * NTHR] = 0.0f;
    }
    // bias sums for this block's 64 gate-columns (index n = gate*16 + jj)
    if (tid < 64) {
        int wr = (tid >> 4) * HID + j0 + (tid & 15);
        bs1[tid] = bih1[wr] + bhh1[wr];
        bs2[tid] = bih2[wr] + bhh2[wr];
    }
    chunk_sync(mc);

    float c1r[4], c2r[4];
#pragma unroll
    for (int i = 0; i < 4; i++) { c1r[i] = 0.0f; c2r[i] = 0.0f; }

    unsigned long long acc[2][4];

#pragma unroll 1
    for (int t = 0; t < TT; t++) {
        const float* h1p = (t == 0) ? g_zero : ((t & 1) ? g_h1a : g_h1b);
        float*       h1c = (t & 1) ? g_h1b : g_h1a;

        // ---- layer 1: gates = x_t @ Wih1^T + h1prev @ Whh1^T --------------
        Seg s0 { x + (size_t)m0 * (TT * IND) + (size_t)t * IND, (size_t)(TT * IND), Wih1, IND };
        Seg s1 { h1p + (size_t)m0 * HID, HID, Whh1, HID };
        gates_gemm(s0, IND / 32, s1, HID / 32, pool, j0, tid, am, an, acc);
        acc_to_cs(Cs, acc, am, an);
        __syncthreads();
        cell_update(Cs, bs1, c1r, h1c, m0, j0, tid);
        chunk_sync(mc);                                // h1(t) visible chunk-wide

        // ---- layer 2: gates = h1(t) @ Wih2^T + h2(t-1) @ Whh2^T -----------
        const float* h2p = (t == 0) ? g_zero : (g_H2 + (size_t)(t - 1) * BSZ * HID);
        float*       h2c = g_H2 + (size_t)t * BSZ * HID;
        Seg s2 { h1c + (size_t)m0 * HID, HID, Wih2, HID };
        Seg s3 { h2p + (size_t)m0 * HID, HID, Whh2, HID };
        gates_gemm(s2, HID / 32, s3, HID / 32, pool, j0, tid, am, an, acc);
        acc_to_cs(Cs, acc, am, an);
        __syncthreads();
        cell_update(Cs, bs2, c2r, h2c, m0, j0, tid);
        chunk_sync(mc);                                // h2(t) visible chunk-wide
    }
}

// ============================================================================
// Output linear: out[b,t,:] = H2[t,b,:] @ Wlin^T + blin
// M = T*B = 131072 (row r = t*256+b), N = 128, K = 512. Fully parallel.
// ============================================================================
__global__ __launch_bounds__(NTHR, 1) void linear_kernel(
    const float* __restrict__ Wl, const float* __restrict__ bl,
    float* __restrict__ out)
{
    __shared__ __align__(16) float smem[4096];
    float* As = smem;
    float* Bs = smem + 2048;

    const int tid  = threadIdx.x;
    const int r0   = blockIdx.x * 64;
    const int n0   = blockIdx.y * 64;
    const int lane = tid & 31;
    const int warp = tid >> 5;
    const int am   = (warp & 1) * 32 + (lane & 7) * 4;
    const int an   = (warp >> 1) * 16 + (lane >> 3) * 4;
    const float* H2 = g_H2;

    unsigned long long acc[2][4];
#pragma unroll
    for (int i = 0; i < 2; i++)
#pragma unroll
        for (int j = 0; j < 4; j++) acc[i][j] = 0ull;

#pragma unroll 1
    for (int k0 = 0; k0 < HID; k0 += 32) {
        __syncthreads();
#pragma unroll
        for (int i = 0; i < 2; i++) {
            int lin = tid + i * NTHR;
            int m = lin >> 3, k4 = (lin & 7) * 4;
            int xsw = m ^ k4;
            float4 v = *(const float4*)(H2 + (size_t)(r0 + m) * HID + k0 + k4);
            As[(k4 + 0) * 64 + xsw] = v.x;
            As[(k4 + 1) * 64 + xsw] = v.y;
            As[(k4 + 2) * 64 + xsw] = v.z;
            As[(k4 + 3) * 64 + xsw] = v.w;
            float4 w = *(const float4*)(Wl + (size_t)(n0 + m) * HID + k0 + k4);
            Bs[(k4 + 0) * 64 + xsw] = w.x;
            Bs[(k4 + 1) * 64 + xsw] = w.y;
            Bs[(k4 + 2) * 64 + xsw] = w.z;
            Bs[(k4 + 3) * 64 + xsw] = w.w;
        }
        __syncthreads();
        mm_tile(As, Bs, am, an, acc);
    }

#pragma unroll
    for (int mp = 0; mp < 2; mp++) {
#pragma unroll
        for (int half = 0; half < 2; half++) {
            int r = r0 + am + mp * 2 + half;
            int t = r >> 8;
            int b = r & 255;
            float* orow = out + (size_t)b * TT * IND + (size_t)t * IND;
#pragma unroll
            for (int c = 0; c < 4; c++) {
                int col = n0 + an + c;
                float v = half ? hi32(acc[mp][c]) : lo32(acc[mp][c]);
                orow[col] = v + bl[col];
            }
        }
    }
}

extern "C" void kernel_launch(void* const* d_in, const int* in_sizes, int n_in,
                              void* d_out, int out_size)
{
    const float* x    = (const float*)d_in[0];
    // d_in[1] = future (0 for this problem)
    const float* Wih1 = (const float*)d_in[2];
    const float* Whh1 = (const float*)d_in[3];
    const float* bih1 = (const float*)d_in[4];
    const float* bhh1 = (const float*)d_in[5];
    const float* Wih2 = (const float*)d_in[6];
    const float* Whh2 = (const float*)d_in[7];
    const float* bih2 = (const float*)d_in[8];
    const float* bhh2 = (const float*)d_in[9];
    const float* Wlin = (const float*)d_in[10];
    const float* blin = (const float*)d_in[11];
    float* out = (float*)d_out;

    lstm_persistent<<<NBLK, NTHR>>>(x, Wih1, Whh1, bih1, bhh1,
                                    Wih2, Whh2, bih2, bhh2);

    linear_kernel<<<dim3((TT * BSZ) / 64, IND / 64), NTHR>>>(Wlin, blin, out);
}